// round 11
// baseline (speedup 1.0000x reference)
#include <cuda_runtime.h>
#include <cstdint>

#define NUM_ANCHORS 145152
#define NUM_CH 85
#define INV_IMG (1.0f / 1536.0f)
#define ROWS_PER_TILE 128
#define THREADS 128
#define NUM_TILES (NUM_ANCHORS / ROWS_PER_TILE)        // 1134
#define TILE_FLOATS (ROWS_PER_TILE * NUM_CH)           // 10880
#define TILE_F4 (TILE_FLOATS / 4)                      // 2720
#define SMEM_BYTES (2 * TILE_FLOATS * 4)               // 87040 B

// d_out layout (fp32), reference tuple order, flattened:
//   [0 .. 4N)    bboxes     (N,4) = x0, y0, x1, y1
//   [4N .. 5N)   scores     (N,)
//   [5N .. 6N)   class_pred (N,)  (as float)
//   [6N .. 12N)  detections (N,6) = x0, y0, x1, y1, conf, cls

__device__ __forceinline__ unsigned smem_u32(const void* p) {
    unsigned a;
    asm("{ .reg .u64 t; cvta.to.shared.u64 t, %1; cvt.u32.u64 %0, t; }"
        : "=r"(a) : "l"(p));
    return a;
}

__device__ __forceinline__ void cp_async16(unsigned dst, const void* src) {
    asm volatile("cp.async.cg.shared.global [%0], [%1], 16;"
                 :: "r"(dst), "l"(src));
}

// Whole block stages one 128-row tile (43520 B = 2720 float4, contiguous).
// 21-22 cp.async per thread. Caller commits.
__device__ __forceinline__ void issue_tile_load(unsigned dst0,
                                                const float* __restrict__ pred,
                                                int tile, int tid)
{
    const float4* src = (const float4*)(pred + (long long)tile * TILE_FLOATS);
    #pragma unroll
    for (int j = 0; j < TILE_F4 / THREADS; ++j)      // 21 full rounds
        cp_async16(dst0 + (tid + j * THREADS) * 16, src + tid + j * THREADS);
    if (tid < TILE_F4 - (TILE_F4 / THREADS) * THREADS)  // remainder: 32
        cp_async16(dst0 + (tid + (TILE_F4 / THREADS) * THREADS) * 16,
                   src + tid + (TILE_F4 / THREADS) * THREADS);
}

// Thread-per-anchor decode from smem (row stride 85, odd -> conflict-free).
__device__ __forceinline__ void compute_tile(const float* __restrict__ s_base,
                                             float* __restrict__ out,
                                             int tile, int tid)
{
    const float* s = s_base + tid * NUM_CH;
    const int anchor = tile * ROWS_PER_TILE + tid;

    float cx  = s[0];
    float cy  = s[1];
    float w   = s[2];
    float h   = s[3];
    float obj = s[4];

    // argmax over classes 5..84, lowest index wins ties (strict >)
    float best = s[5];
    int   bi   = 0;
    #pragma unroll
    for (int c = 6; c < NUM_CH; ++c) {
        float v = s[c];
        if (v > best) { best = v; bi = c - 5; }
    }

    float bx = cx * INV_IMG;
    float by = cy * INV_IMG;
    float bw = w  * INV_IMG;
    float bh = h  * INV_IMG;
    float x0 = bx - bw * 0.5f;
    float y0 = by - bh * 0.5f;
    float x1 = bx + bw * 0.5f;
    float y1 = by + bh * 0.5f;

    float conf  = best;
    float clsf  = (float)bi;
    float score = obj * conf;

    float* out_sc  = out + (long long)NUM_ANCHORS * 4;
    float* out_cls = out + (long long)NUM_ANCHORS * 5;
    float* out_det = out + (long long)NUM_ANCHORS * 6;

    ((float4*)out)[anchor] = make_float4(x0, y0, x1, y1);
    out_sc[anchor]  = score;
    out_cls[anchor] = clsf;

    float2* det = (float2*)(out_det + (long long)anchor * 6);
    det[0] = make_float2(x0, y0);
    det[1] = make_float2(x1, y1);
    det[2] = make_float2(conf, clsf);
}

__global__ __launch_bounds__(THREADS)
void yolo_decode_kernel(const float* __restrict__ pred,
                        float* __restrict__ out,
                        int n_blocks_total)
{
    extern __shared__ float smem[];
    float* bufs[2] = { smem, smem + TILE_FLOATS };
    unsigned dsts[2] = { smem_u32(bufs[0]), smem_u32(bufs[1]) };

    const int tid = threadIdx.x;

    int tile = blockIdx.x;
    if (tile >= NUM_TILES) return;

    // prologue: block-wide load of tile into buffer 0
    issue_tile_load(dsts[0], pred, tile, tid);
    asm volatile("cp.async.commit_group;");

    int cur = 0;
    while (true) {
        int nt = tile + n_blocks_total;
        if (nt < NUM_TILES) {
            // loads for the NEXT tile fly while we compute the current one
            issue_tile_load(dsts[cur ^ 1], pred, nt, tid);
            asm volatile("cp.async.commit_group;");
            asm volatile("cp.async.wait_group 1;");
        } else {
            asm volatile("cp.async.wait_group 0;");
        }
        __syncthreads();                     // tile data visible to all threads

        compute_tile(bufs[cur], out, tile, tid);

        if (nt >= NUM_TILES) break;
        __syncthreads();   // all reads of bufs[cur] done before it is reloaded
        cur ^= 1;
        tile = nt;
    }
}

extern "C" void kernel_launch(void* const* d_in, const int* in_sizes, int n_in,
                              void* d_out, int out_size)
{
    const float* pred = (const float*)d_in[0];
    // d_in[1] = score_threshold — unused by the reference computation.
    float* out = (float*)d_out;

    cudaFuncSetAttribute(yolo_decode_kernel,
                         cudaFuncAttributeMaxDynamicSharedMemorySize,
                         SMEM_BYTES);

    const int blocks = 296;                 // 2 per SM, persistent grid-stride
    yolo_decode_kernel<<<blocks, THREADS, SMEM_BYTES>>>(pred, out, blocks);
}

// round 12
// speedup vs baseline: 1.0269x; 1.0269x over previous
#include <cuda_runtime.h>
#include <cstdint>

#define NUM_ANCHORS 145152
#define NUM_CH 85
#define INV_IMG (1.0f / 1536.0f)
#define ROWS_PER_TILE 128
#define THREADS 256
#define NUM_TILES (NUM_ANCHORS / ROWS_PER_TILE)        // 1134
#define TILE_FLOATS (ROWS_PER_TILE * NUM_CH)           // 10880
#define TILE_BYTES (TILE_FLOATS * 4)                   // 43520
#define SMEM_BYTES (128 + 2 * TILE_BYTES)              // 87168 B

// d_out layout (fp32), reference tuple order, flattened:
//   [0 .. 4N)    bboxes     (N,4) = x0, y0, x1, y1
//   [4N .. 5N)   scores     (N,)
//   [5N .. 6N)   class_pred (N,)  (as float)
//   [6N .. 12N)  detections (N,6) = x0, y0, x1, y1, conf, cls

__device__ __forceinline__ unsigned smem_u32(const void* p) {
    unsigned a;
    asm("{ .reg .u64 t; cvta.to.shared.u64 t, %1; cvt.u32.u64 %0, t; }"
        : "=r"(a) : "l"(p));
    return a;
}

__device__ __forceinline__ void mbar_init(unsigned mbar, unsigned count) {
    asm volatile("mbarrier.init.shared.b64 [%0], %1;" :: "r"(mbar), "r"(count)
                 : "memory");
}

__device__ __forceinline__ void mbar_expect_tx(unsigned mbar, unsigned bytes) {
    asm volatile("mbarrier.arrive.expect_tx.shared.b64 _, [%0], %1;"
                 :: "r"(mbar), "r"(bytes) : "memory");
}

// One-shot bulk copy gmem -> smem (async proxy), completion on mbar.
__device__ __forceinline__ void bulk_load(unsigned dst, const void* src,
                                          unsigned bytes, unsigned mbar) {
    asm volatile(
        "cp.async.bulk.shared::cta.global.mbarrier::complete_tx::bytes "
        "[%0], [%1], %2, [%3];"
        :: "r"(dst), "l"(src), "r"(bytes), "r"(mbar) : "memory");
}

__device__ __forceinline__ void mbar_wait(unsigned mbar, unsigned phase) {
    unsigned done;
    asm volatile(
        "{\n\t"
        ".reg .pred p;\n\t"
        "mbarrier.try_wait.parity.acquire.cta.shared::cta.b64 p, [%1], %2;\n\t"
        "selp.b32 %0, 1, 0, p;\n\t"
        "}"
        : "=r"(done) : "r"(mbar), "r"(phase) : "memory");
    if (!done) {
        asm volatile(
            "{\n\t"
            ".reg .pred P1;\n\t"
            "WL_%=:\n\t"
            "mbarrier.try_wait.parity.acquire.cta.shared::cta.b64 P1, [%0], %1, 0x989680;\n\t"
            "@P1 bra.uni WD_%=;\n\t"
            "bra.uni WL_%=;\n\t"
            "WD_%=:\n\t"
            "}"
            :: "r"(mbar), "r"(phase) : "memory");
    }
}

// Pair-lane decode: 2 threads per row; even lane ch 0..39, odd lane 40..79.
__device__ __forceinline__ void compute_tile(const float* __restrict__ s_base,
                                             float* __restrict__ out,
                                             int tile, int tid)
{
    const unsigned FULL = 0xffffffffu;
    const int row  = tid >> 1;                // 0..127
    const int half = tid & 1;
    const float* s = s_base + row * NUM_CH;   // stride 85 -> conflict-free
    const int anchor = tile * ROWS_PER_TILE + row;

    float cx  = s[0];
    float cy  = s[1];
    float w   = s[2];
    float h   = s[3];
    float obj = s[4];

    // 40-channel scan per lane, strict > keeps lowest index on ties.
    const int base = 40 * half;
    const float* cs = s + 5 + base;
    float bv = cs[0];
    int   bi = base;
    #pragma unroll
    for (int k = 1; k < 40; ++k) {
        float v = cs[k];
        if (v > bv) { bv = v; bi = base + k; }
    }

    // Combine pair halves (lowest index wins ties).
    float ov = __shfl_xor_sync(FULL, bv, 1);
    int   oi = __shfl_xor_sync(FULL, bi, 1);
    if (ov > bv || (ov == bv && oi < bi)) { bv = ov; bi = oi; }

    float bx = cx * INV_IMG;
    float by = cy * INV_IMG;
    float bw = w  * INV_IMG;
    float bh = h  * INV_IMG;
    float x0 = bx - bw * 0.5f;
    float y0 = by - bh * 0.5f;
    float x1 = bx + bw * 0.5f;
    float y1 = by + bh * 0.5f;

    float conf  = bv;
    float clsf  = (float)bi;
    float score = obj * conf;

    float* out_sc  = out + (long long)NUM_ANCHORS * 4;
    float* out_cls = out + (long long)NUM_ANCHORS * 5;
    float* out_det = out + (long long)NUM_ANCHORS * 6;

    if (half == 0) {
        ((float4*)out)[anchor] = make_float4(x0, y0, x1, y1);
        out_sc[anchor]  = score;
        out_cls[anchor] = clsf;
    } else {
        float2* det = (float2*)(out_det + (long long)anchor * 6);
        det[0] = make_float2(x0, y0);
        det[1] = make_float2(x1, y1);
        det[2] = make_float2(conf, clsf);
    }
}

__global__ __launch_bounds__(THREADS)
void yolo_decode_kernel(const float* __restrict__ pred,
                        float* __restrict__ out,
                        int n_blocks_total)
{
    extern __shared__ float smem[];
    char* sbase = (char*)smem;
    unsigned mbar[2] = { smem_u32(sbase), smem_u32(sbase + 8) };
    float* bufs[2] = { (float*)(sbase + 128),
                       (float*)(sbase + 128) + TILE_FLOATS };
    unsigned dsts[2] = { smem_u32(bufs[0]), smem_u32(bufs[1]) };

    const int tid = threadIdx.x;

    if (tid == 0) {
        mbar_init(mbar[0], 1);
        mbar_init(mbar[1], 1);
        asm volatile("fence.proxy.async.shared::cta;" ::: "memory");
    }
    __syncthreads();

    int tile = blockIdx.x;
    if (tile >= NUM_TILES) return;

    int phase0 = 0, phase1 = 0;

    // prologue: bulk-load tile into buffer 0 (single thread, one instruction)
    if (tid == 0) {
        mbar_expect_tx(mbar[0], TILE_BYTES);
        bulk_load(dsts[0], pred + (long long)tile * TILE_FLOATS,
                  TILE_BYTES, mbar[0]);
    }

    int cur = 0;
    while (true) {
        int nt = tile + n_blocks_total;
        if (nt < NUM_TILES && tid == 0) {
            // next tile's load flies while we compute the current one
            mbar_expect_tx(mbar[cur ^ 1], TILE_BYTES);
            bulk_load(dsts[cur ^ 1], pred + (long long)nt * TILE_FLOATS,
                      TILE_BYTES, mbar[cur ^ 1]);
        }

        // every thread waits on the current buffer's barrier (acquire)
        mbar_wait(mbar[cur], cur == 0 ? phase0 : phase1);

        compute_tile(bufs[cur], out, tile, tid);

        if (nt >= NUM_TILES) break;

        // flip consumed phase; barrier before buffer reuse (issued next iter)
        if (cur == 0) phase0 ^= 1; else phase1 ^= 1;
        __syncthreads();
        cur ^= 1;
        tile = nt;
    }
}

extern "C" void kernel_launch(void* const* d_in, const int* in_sizes, int n_in,
                              void* d_out, int out_size)
{
    const float* pred = (const float*)d_in[0];
    // d_in[1] = score_threshold — unused by the reference computation.
    float* out = (float*)d_out;

    cudaFuncSetAttribute(yolo_decode_kernel,
                         cudaFuncAttributeMaxDynamicSharedMemorySize,
                         SMEM_BYTES);

    const int blocks = 296;                 // 2 per SM, persistent grid-stride
    yolo_decode_kernel<<<blocks, THREADS, SMEM_BYTES>>>(pred, out, blocks);
}